// round 3
// baseline (speedup 1.0000x reference)
#include <cuda_runtime.h>
#include <cuda_bf16.h>

#define TABLE_SCALE 1024.0f   // 2^10
#define TABLE_SIZE  4096
#define TABLE_MAX   (TABLE_SIZE - 1)
#define UNROLL 4
#define THREADS 256
#define GRID_CTAS (152 * 8)   // persistent: 1 full wave on GB300 (152 SMs, 8 CTAs/SM)

__device__ __forceinline__ int table_idx(float x) {
    int c = (int)(fabsf(x) * TABLE_SCALE);   // truncation toward zero
    return min(c, TABLE_MAX);
}

__global__ void __launch_bounds__(THREADS) SecGELU_kernel(
    const float4* __restrict__ x,
    const float* __restrict__ table,
    float4* __restrict__ out,
    int n4)
{
    __shared__ float table_s[TABLE_SIZE];

    // Cooperative table fill: 4096 floats = 1024 float4, 4 per thread.
    {
        const float4* t4 = (const float4*)table;
        float4* s4 = (float4*)table_s;
        #pragma unroll
        for (int k = 0; k < TABLE_SIZE / 4 / THREADS; k++)
            s4[threadIdx.x + k * THREADS] = t4[threadIdx.x + k * THREADS];
    }
    __syncthreads();

    const int stride = gridDim.x * THREADS * UNROLL;

    for (int base = blockIdx.x * (THREADS * UNROLL) + threadIdx.x;
         base < n4;
         base += stride)
    {
        bool full = (base + (UNROLL - 1) * THREADS) < n4;

        if (full) {
            float4 v[UNROLL];
            #pragma unroll
            for (int k = 0; k < UNROLL; k++)
                v[k] = __ldcs(x + base + k * THREADS);      // front-batched streaming loads

            // Batch all 16 independent gathers (LDS pipe, separate from L1tex)
            float t[UNROLL][4];
            #pragma unroll
            for (int k = 0; k < UNROLL; k++) {
                t[k][0] = table_s[table_idx(v[k].x)];
                t[k][1] = table_s[table_idx(v[k].y)];
                t[k][2] = table_s[table_idx(v[k].z)];
                t[k][3] = table_s[table_idx(v[k].w)];
            }

            #pragma unroll
            for (int k = 0; k < UNROLL; k++) {
                float4 r;
                r.x = (v[k].x >= 0.0f ? v[k].x : 0.0f) - t[k][0];
                r.y = (v[k].y >= 0.0f ? v[k].y : 0.0f) - t[k][1];
                r.z = (v[k].z >= 0.0f ? v[k].z : 0.0f) - t[k][2];
                r.w = (v[k].w >= 0.0f ? v[k].w : 0.0f) - t[k][3];
                __stcs(out + base + k * THREADS, r);
            }
        } else {
            #pragma unroll
            for (int k = 0; k < UNROLL; k++) {
                int i = base + k * THREADS;
                if (i < n4) {
                    float4 v = __ldcs(x + i);
                    float4 r;
                    r.x = (v.x >= 0.0f ? v.x : 0.0f) - table_s[table_idx(v.x)];
                    r.y = (v.y >= 0.0f ? v.y : 0.0f) - table_s[table_idx(v.y)];
                    r.z = (v.z >= 0.0f ? v.z : 0.0f) - table_s[table_idx(v.z)];
                    r.w = (v.w >= 0.0f ? v.w : 0.0f) - table_s[table_idx(v.w)];
                    __stcs(out + i, r);
                }
            }
        }
    }
}

// Tail handler for n not divisible by 4 (not needed for 2^26, but safe).
__global__ void SecGELU_tail(
    const float* __restrict__ x,
    const float* __restrict__ table,
    float* __restrict__ out,
    int start, int n)
{
    int i = start + blockIdx.x * blockDim.x + threadIdx.x;
    if (i >= n) return;
    float v = x[i];
    int c = table_idx(v);
    out[i] = (v >= 0.0f ? v : 0.0f) - __ldg(table + c);
}

extern "C" void kernel_launch(void* const* d_in, const int* in_sizes, int n_in,
                              void* d_out, int out_size) {
    const float* x     = (const float*)d_in[0];
    const float* table = (const float*)d_in[1];
    float* out = (float*)d_out;

    int n  = in_sizes[0];
    int n4 = n >> 2;

    if (n4 > 0) {
        int per_block = THREADS * UNROLL;
        int needed = (n4 + per_block - 1) / per_block;
        int blocks = needed < GRID_CTAS ? needed : GRID_CTAS;
        SecGELU_kernel<<<blocks, THREADS>>>(
            (const float4*)x, table, (float4*)out, n4);
    }
    int rem = n - (n4 << 2);
    if (rem > 0) {
        SecGELU_tail<<<1, 32>>>(x, table, out, n4 << 2, n);
    }
}

// round 4
// speedup vs baseline: 1.1030x; 1.1030x over previous
#include <cuda_runtime.h>
#include <cuda_bf16.h>

#define TABLE_SCALE 1024.0f   // 2^10
#define TABLE_MAX   4095      // TABLE_SIZE - 1
#define UNROLL 4
#define THREADS 256
#define CHUNK_F4 (THREADS * UNROLL)     // 1024 float4 = 16 KB per chunk
#define NUM_CTAS (152 * 8)              // one full wave on GB300

__device__ unsigned int g_ticket;

__device__ __forceinline__ float secgelu_one(float x, const float* __restrict__ table) {
    float a = fabsf(x);
    int c = (int)(a * TABLE_SCALE);          // truncation toward zero, a >= 0
    c = min(c, TABLE_MAX);
    float relu_x = x >= 0.0f ? x : 0.0f;
    return relu_x - __ldg(table + c);
}

__device__ __forceinline__ float4 secgelu_vec4(float4 v, const float* __restrict__ table) {
    float4 r;
    r.x = secgelu_one(v.x, table);
    r.y = secgelu_one(v.y, table);
    r.z = secgelu_one(v.z, table);
    r.w = secgelu_one(v.w, table);
    return r;
}

__global__ void SecGELU_init(unsigned int start) {
    g_ticket = start;
}

// Persistent work-stealing kernel: each CTA processes 16 KB chunks handed out
// by a global ticket counter. Front-batched independent streaming loads
// (MLP_p1 = UNROLL) hide DRAM latency; .cs hints keep the 512 MiB streams out
// of L2 while the 16 KB table stays L1-resident via __ldg.
__global__ void __launch_bounds__(THREADS) SecGELU_kernel(
    const float4* __restrict__ x,
    const float* __restrict__ table,
    float4* __restrict__ out,
    int n4, unsigned int num_chunks)
{
    __shared__ unsigned int s_chunk;
    unsigned int chunk = blockIdx.x;

    while (chunk < num_chunks) {
        int base = (int)(chunk * CHUNK_F4) + threadIdx.x;
        bool full = (base + (UNROLL - 1) * THREADS) < n4;

        if (full) {
            float4 v[UNROLL];
            #pragma unroll
            for (int k = 0; k < UNROLL; k++)
                v[k] = __ldcs(x + base + k * THREADS);   // front-batched, independent

            #pragma unroll
            for (int k = 0; k < UNROLL; k++)
                __stcs(out + base + k * THREADS, secgelu_vec4(v[k], table));
        } else {
            #pragma unroll
            for (int k = 0; k < UNROLL; k++) {
                int i = base + k * THREADS;
                if (i < n4) {
                    float4 t = __ldcs(x + i);
                    __stcs(out + i, secgelu_vec4(t, table));
                }
            }
        }

        // Grab next chunk (one atomic per CTA per chunk; broadcast via smem).
        if (threadIdx.x == 0)
            s_chunk = atomicAdd(&g_ticket, 1u);
        __syncthreads();
        chunk = s_chunk;
        __syncthreads();   // all threads read s_chunk before tid0 rewrites it
    }
}

// Tail handler for n not divisible by 4 (not needed for 2^26, but safe).
__global__ void SecGELU_tail(
    const float* __restrict__ x,
    const float* __restrict__ table,
    float* __restrict__ out,
    int start, int n)
{
    int i = start + blockIdx.x * blockDim.x + threadIdx.x;
    if (i >= n) return;
    out[i] = secgelu_one(x[i], table);
}

extern "C" void kernel_launch(void* const* d_in, const int* in_sizes, int n_in,
                              void* d_out, int out_size) {
    const float* x     = (const float*)d_in[0];
    const float* table = (const float*)d_in[1];
    float* out = (float*)d_out;

    int n  = in_sizes[0];
    int n4 = n >> 2;

    if (n4 > 0) {
        unsigned int num_chunks = (unsigned int)((n4 + CHUNK_F4 - 1) / CHUNK_F4);
        unsigned int ctas = num_chunks < NUM_CTAS ? num_chunks : NUM_CTAS;

        SecGELU_init<<<1, 1>>>(ctas);   // ticket starts past the pre-assigned chunks
        SecGELU_kernel<<<ctas, THREADS>>>(
            (const float4*)x, table, (float4*)out, n4, num_chunks);
    }
    int rem = n - (n4 << 2);
    if (rem > 0) {
        SecGELU_tail<<<1, 32>>>(x, table, out, n4 << 2, n);
    }
}

// round 5
// speedup vs baseline: 1.1050x; 1.0019x over previous
#include <cuda_runtime.h>
#include <cuda_bf16.h>

#define TABLE_SCALE 1024.0f   // 2^10
#define TABLE_MAX   4095      // TABLE_SIZE - 1
#define UNROLL 8
#define THREADS 256

__device__ __forceinline__ float secgelu_one(float x, const float* __restrict__ table) {
    float a = fabsf(x);
    int c = (int)(a * TABLE_SCALE);          // truncation toward zero, a >= 0
    c = min(c, TABLE_MAX);
    float relu_x = x >= 0.0f ? x : 0.0f;
    return relu_x - __ldg(table + c);
}

__device__ __forceinline__ float4 secgelu_vec4(float4 v, const float* __restrict__ table) {
    float4 r;
    r.x = secgelu_one(v.x, table);
    r.y = secgelu_one(v.y, table);
    r.z = secgelu_one(v.z, table);
    r.w = secgelu_one(v.w, table);
    return r;
}

// Flat grid (persistence regressed in R3/R4). Each thread front-batches
// 8 independent LDG.128s (4 KB in flight per warp) so DRAM stays fed even
// while table-gather replay wavefronts occupy the L1tex queue. Streaming
// .cs hints keep the 512 MiB x/out streams out of L2; the 16 KB table stays
// L1-resident via __ldg.
__global__ void SecGELU_kernel(
    const float4* __restrict__ x,
    const float* __restrict__ table,
    float4* __restrict__ out,
    int n4)
{
    int base = blockIdx.x * (THREADS * UNROLL) + threadIdx.x;

    if (base + (UNROLL - 1) * THREADS < n4) {
        float4 v[UNROLL];
        #pragma unroll
        for (int k = 0; k < UNROLL; k++)
            v[k] = __ldcs(x + base + k * THREADS);   // front-batched, independent

        #pragma unroll
        for (int k = 0; k < UNROLL; k++)
            __stcs(out + base + k * THREADS, secgelu_vec4(v[k], table));
    } else {
        #pragma unroll
        for (int k = 0; k < UNROLL; k++) {
            int i = base + k * THREADS;
            if (i < n4) {
                float4 t = __ldcs(x + i);
                __stcs(out + i, secgelu_vec4(t, table));
            }
        }
    }
}

// Tail handler for n not divisible by 4 (not needed for 2^26, but safe).
__global__ void SecGELU_tail(
    const float* __restrict__ x,
    const float* __restrict__ table,
    float* __restrict__ out,
    int start, int n)
{
    int i = start + blockIdx.x * blockDim.x + threadIdx.x;
    if (i >= n) return;
    out[i] = secgelu_one(x[i], table);
}

extern "C" void kernel_launch(void* const* d_in, const int* in_sizes, int n_in,
                              void* d_out, int out_size) {
    const float* x     = (const float*)d_in[0];
    const float* table = (const float*)d_in[1];
    float* out = (float*)d_out;

    int n  = in_sizes[0];
    int n4 = n >> 2;

    if (n4 > 0) {
        int per_block = THREADS * UNROLL;
        int blocks = (n4 + per_block - 1) / per_block;
        SecGELU_kernel<<<blocks, THREADS>>>(
            (const float4*)x, table, (float4*)out, n4);
    }
    int rem = n - (n4 << 2);
    if (rem > 0) {
        SecGELU_tail<<<1, 32>>>(x, table, out, n4 << 2, n);
    }
}